// round 13
// baseline (speedup 1.0000x reference)
#include <cuda_runtime.h>
#include <cstdint>
#include <math.h>

// Problem constants
constexpr int B_  = 4;
constexpr int N_  = 1024;
constexpr int D_  = 256;
constexpr int H_  = 4;
constexpr int L_  = 2;
constexpr int BN_ = B_ * N_;        // 4096
constexpr int FD_ = D_ * H_ * L_;   // 2048

// Scratch (static device globals)
__device__ float g_inhi[BN_ * 512];             // 8 MB  [gcn|rel] tf32-hi
__device__ float g_inlo[BN_ * 512];             // 8 MB  [gcn|rel] tf32-lo
__device__ float g_wqhi[512 * D_];
__device__ float g_wqlo[512 * D_];
__device__ float g_wkhi[D_ * D_];
__device__ float g_wklo[D_ * D_];
__device__ float g_qhi[BN_ * D_];
__device__ float g_qlo[BN_ * D_];
__device__ float g_khi[BN_ * D_];
__device__ float g_klo[BN_ * D_];
__device__ float g_attn[16 * N_ * N_];          // 64 MB
__device__ float g_denom[16 * N_];
__device__ float g_tmp[16 * N_ * D_];           // 16 MB
__device__ float g_final[BN_ * FD_];            // 32 MB
__device__ float g_part[4 * BN_ * D_];          // 16 MB
__device__ float g_wgr[8 * D_ * D_];            // rounded W_gcn
__device__ float g_wor[FD_ * D_];               // rounded W_out
__device__ uint32_t g_adjbits[B_ * N_ * (N_ / 32)];

// ===========================================================================
// helpers
// ===========================================================================
__device__ __forceinline__ uint32_t smem_u32(const void* p) {
    uint32_t a;
    asm("{ .reg .u64 t; cvta.to.shared.u64 t, %1; cvt.u32.u64 %0, t; }" : "=r"(a) : "l"(p));
    return a;
}
__device__ __forceinline__ uint32_t f2tf(float x) {
    uint32_t r;
    asm("cvt.rna.tf32.f32 %0, %1;" : "=r"(r) : "f"(x));
    return r;
}
__device__ __forceinline__ float rna(float x) { return __uint_as_float(f2tf(x)); }

__device__ __forceinline__ void mma16n8k8(float d[4], const uint32_t a[4],
                                          const uint32_t b[2]) {
    asm volatile(
        "mma.sync.aligned.m16n8k8.row.col.f32.tf32.tf32.f32 "
        "{%0,%1,%2,%3}, {%4,%5,%6,%7}, {%8,%9}, {%0,%1,%2,%3};"
        : "+f"(d[0]), "+f"(d[1]), "+f"(d[2]), "+f"(d[3])
        : "r"(a[0]), "r"(a[1]), "r"(a[2]), "r"(a[3]), "r"(b[0]), "r"(b[1]));
}

#define CP_A16(dst, src) \
    asm volatile("cp.async.cg.shared.global [%0], [%1], 16;" :: "r"(dst), "l"(src))
#define CP_COMMIT() asm volatile("cp.async.commit_group;")
#define CP_WAIT(n)  asm volatile("cp.async.wait_group %0;" :: "n"(n))

// ===========================================================================
// 256-thread pipelined tf32 mma core: block tile 128x256, K-chunk 32,
// 8 warps (2m x 4n), warp tile 64x64, 3-stage cp.async. Accumulates into c.
// (64x64 warp tile: 1.0 LDS per HMMA vs 1.5 for 32x64 — issue-bound fix)
// ===========================================================================
constexpr int AS_STR = 36;
constexpr int BS_STR = 264;
constexpr int ASZ = 128 * AS_STR;          // 4608 words
constexpr int BSZ = 32 * BS_STR;           // 8448 words
constexpr int STG = ASZ + BSZ;             // 13056 words
constexpr int MMA_SMEM = 3 * STG * 4;      // 156672 B

__device__ __forceinline__ void mma_issue(const float* __restrict__ A, int lda,
                                          const float* __restrict__ B, int ldb,
                                          int kt, uint32_t sb) {
    const int tid = threadIdx.x;
    const uint32_t da = sb + (uint32_t)((kt % 3) * STG) * 4u;
    const uint32_t db = da + (uint32_t)ASZ * 4u;
    const float* Ak = A + kt * 32;
    const float* Bk = B + (size_t)(kt * 32) * ldb;
#pragma unroll
    for (int e = 0; e < 4; e++) {
        int idx = tid + 256 * e;
        int row = idx >> 3;
        int c4 = idx & 7;
        CP_A16(da + (uint32_t)(row * AS_STR + c4 * 4) * 4u,
               Ak + (size_t)row * lda + c4 * 4);
    }
#pragma unroll
    for (int e = 0; e < 8; e++) {
        int idx = tid + 256 * e;
        int kr = idx >> 6;
        int c4 = idx & 63;
        CP_A16(db + (uint32_t)(kr * BS_STR + c4 * 4) * 4u,
               Bk + (size_t)kr * ldb + c4 * 4);
    }
}

__device__ __forceinline__ void mma_core(const float* __restrict__ A, int lda,
                                         const float* __restrict__ B, int ldb,
                                         int K, float c[4][8][4], uint32_t* sm) {
    const int tid = threadIdx.x;
    const uint32_t sb = smem_u32(sm);
    const int lane = tid & 31, wid = tid >> 5;
    const int wm = (wid >> 2) * 64, wn = (wid & 3) * 64;
    const int qr = lane >> 2, qk = lane & 3;
    const int niter = K >> 5;

    mma_issue(A, lda, B, ldb, 0, sb); CP_COMMIT();
    mma_issue(A, lda, B, ldb, 1, sb); CP_COMMIT();

    for (int kt = 0; kt < niter; kt++) {
        if (kt + 2 < niter) mma_issue(A, lda, B, ldb, kt + 2, sb);
        CP_COMMIT();
        CP_WAIT(1);
        __syncthreads();
        const uint32_t* sA = sm + (kt % 3) * STG;
        const uint32_t* sB = sA + ASZ;
#pragma unroll
        for (int kk = 0; kk < 4; kk++) {
            const int k0 = kk * 8;
            uint32_t af[4][4];
#pragma unroll
            for (int mi = 0; mi < 4; mi++) {
                const int rb = wm + mi * 16 + qr;
                af[mi][0] = sA[(rb)     * AS_STR + k0 + qk];
                af[mi][1] = sA[(rb + 8) * AS_STR + k0 + qk];
                af[mi][2] = sA[(rb)     * AS_STR + k0 + qk + 4];
                af[mi][3] = sA[(rb + 8) * AS_STR + k0 + qk + 4];
            }
#pragma unroll
            for (int ni = 0; ni < 8; ni++) {
                uint32_t bf[2];
                bf[0] = sB[(k0 + qk)     * BS_STR + wn + ni * 8 + qr];
                bf[1] = sB[(k0 + qk + 4) * BS_STR + wn + ni * 8 + qr];
#pragma unroll
                for (int mi = 0; mi < 4; mi++)
                    mma16n8k8(c[mi][ni], af[mi], bf);
            }
        }
        __syncthreads();
    }
}

// Epilogue: row = wm+mi*16+qr+half*8, col = wn+ni*8+2qk (cols span 256)
#define EPILOGUE_LOOP(BODY)                                                   \
    do {                                                                      \
        const int lane = threadIdx.x & 31, wid = threadIdx.x >> 5;            \
        const int wm = (wid >> 2) * 64, wn = (wid & 3) * 64;                  \
        const int qr = lane >> 2, qk = lane & 3;                              \
        _Pragma("unroll")                                                     \
        for (int mi = 0; mi < 4; mi++)                                        \
            _Pragma("unroll")                                                 \
            for (int half = 0; half < 2; half++) {                            \
                const int row = wm + mi * 16 + qr + half * 8;                 \
                _Pragma("unroll")                                             \
                for (int ni = 0; ni < 8; ni++) {                              \
                    const int col = wn + ni * 8 + 2 * qk;                     \
                    float v0 = c[mi][ni][half * 2 + 0];                       \
                    float v1 = c[mi][ni][half * 2 + 1];                       \
                    BODY                                                      \
                }                                                             \
            }                                                                 \
    } while (0)

// ===========================================================================
// T[bh] = a[bh] @ X[b] + X[b]  (K=1024) -> g_tmp (rna-rounded)
// grid (8 mtiles, 16 bh), 256 thr
// ===========================================================================
__global__ __launch_bounds__(256) void axpx_mma(const float* __restrict__ gcn, int l) {
    extern __shared__ uint32_t sm[];
    const int bh = blockIdx.y, b = bh >> 2, h = bh & 3;
    const int m0 = blockIdx.x * 128;
    const float* A = g_attn + (size_t)bh * N_ * N_ + (size_t)m0 * N_;
    const float* Xg; const float* Xe; int ldg, lde;
    if (l == 0) {
        Xg = g_inhi + (size_t)b * N_ * 512; ldg = 512;     // hi(gcn) = cols 0..255
        Xe = gcn + (size_t)b * N_ * D_;     lde = D_;
    } else {
        Xg = g_final + (size_t)b * N_ * FD_ + 2 * h * D_; ldg = FD_;
        Xe = Xg; lde = FD_;
    }

    float c[4][8][4] = {};
    mma_core(A, N_, Xg, ldg, N_, c, sm);

    const float* Xa = Xe + (size_t)m0 * lde;
    float* C = g_tmp + (size_t)bh * N_ * D_ + (size_t)m0 * D_;
    EPILOGUE_LOOP({
        v0 = rna(v0 + Xa[(size_t)row * lde + col]);
        v1 = rna(v1 + Xa[(size_t)row * lde + col + 1]);
        *(float2*)(C + (size_t)row * D_ + col) = make_float2(v0, v1);
    });
}

// ===========================================================================
// g_final[:, idx*D:] = relu((T @ W_gcn[idx] + 2*b_gcn[idx]) / denom)  (rounded)
// grid (8 mtiles, 16 bh), K=256
// ===========================================================================
__global__ __launch_bounds__(256) void tw_mma(const float* __restrict__ bg, int l) {
    extern __shared__ uint32_t sm[];
    const int bh = blockIdx.y, b = bh >> 2, h = bh & 3;
    const int idx = h * L_ + l;
    const int m0 = blockIdx.x * 128;
    const float* A = g_tmp + (size_t)bh * N_ * D_ + (size_t)m0 * D_;
    const float* Bw = g_wgr + (size_t)idx * D_ * D_;

    float c[4][8][4] = {};
    mma_core(A, D_, Bw, D_, D_, c, sm);

    float* C = g_final + (size_t)b * N_ * FD_ + (size_t)idx * D_ + (size_t)m0 * FD_;
    const float* dn = g_denom + (size_t)bh * N_ + m0;
    const float* bgp = bg + (size_t)idx * D_;
    EPILOGUE_LOOP({
        const float inv = 1.f / dn[row];
        v0 = rna(fmaxf((v0 + 2.f * bgp[col])     * inv, 0.f));
        v1 = rna(fmaxf((v1 + 2.f * bgp[col + 1]) * inv, 0.f));
        *(float2*)(C + (size_t)row * FD_ + col) = make_float2(v0, v1);
    });
}

// ===========================================================================
// Projections on tensor cores (fp32-accurate via hi/lo 3-mma)
// grid (32 mtiles, 2): z=0 q (K=512), z=1 k (K=256)
// ===========================================================================
__global__ __launch_bounds__(256) void proj_mma(const float* __restrict__ b_Q,
                                                const float* __restrict__ b_K) {
    extern __shared__ uint32_t sm[];
    const int z = blockIdx.y;
    const int m0 = blockIdx.x * 128;
    const float* Ahi = g_inhi + (size_t)m0 * 512;
    const float* Alo = g_inlo + (size_t)m0 * 512;
    const float* Bhi = z ? g_wkhi : g_wqhi;
    const float* Blo = z ? g_wklo : g_wqlo;
    const int K = z ? 256 : 512;

    float c[4][8][4] = {};
    mma_core(Ahi, 512, Bhi, D_, K, c, sm);
    mma_core(Ahi, 512, Blo, D_, K, c, sm);
    mma_core(Alo, 512, Bhi, D_, K, c, sm);

    const float* bias = z ? b_K : b_Q;
    float* Chi = z ? g_khi : g_qhi;
    float* Clo = z ? g_klo : g_qlo;
    EPILOGUE_LOOP({
        float f0 = v0 + bias[col];
        float f1 = v1 + bias[col + 1];
        float h0 = rna(f0);
        float h1 = rna(f1);
        *(float2*)(Chi + (size_t)(m0 + row) * D_ + col) = make_float2(h0, h1);
        *(float2*)(Clo + (size_t)(m0 + row) * D_ + col) =
            make_float2(rna(f0 - h0), rna(f1 - h1));
    });
}

// ===========================================================================
// Split-K output GEMM + reduce
// ===========================================================================
__global__ __launch_bounds__(256) void final_mma() {
    extern __shared__ uint32_t sm[];
    const int kc = blockIdx.x, m0 = blockIdx.y * 128;
    const float* A = g_final + (size_t)m0 * FD_ + kc * 512;
    const float* Bw = g_wor + (size_t)kc * 512 * D_;

    float c[4][8][4] = {};
    mma_core(A, FD_, Bw, D_, 512, c, sm);

    float* C = g_part + (size_t)kc * BN_ * D_ + (size_t)m0 * D_;
    EPILOGUE_LOOP({
        *(float2*)(C + (size_t)row * D_ + col) = make_float2(v0, v1);
    });
}

__global__ __launch_bounds__(256) void reduce_final(const float* __restrict__ gcn,
                                                    const float* __restrict__ bo,
                                                    float* __restrict__ out) {
    const int i = blockIdx.x * 256 + threadIdx.x;
    const float4 p0 = ((const float4*)g_part)[i];
    const float4 p1 = ((const float4*)(g_part + (size_t)BN_ * D_))[i];
    const float4 p2 = ((const float4*)(g_part + (size_t)2 * BN_ * D_))[i];
    const float4 p3 = ((const float4*)(g_part + (size_t)3 * BN_ * D_))[i];
    const float4 g  = ((const float4*)gcn)[i];
    const float4 bb = ((const float4*)bo)[i & 63];
    float4 r;
    r.x = g.x + ((p0.x + p1.x) + (p2.x + p3.x)) + bb.x;
    r.y = g.y + ((p0.y + p1.y) + (p2.y + p3.y)) + bb.y;
    r.z = g.z + ((p0.z + p1.z) + (p2.z + p3.z)) + bb.z;
    r.w = g.w + ((p0.w + p1.w) + (p2.w + p3.w)) + bb.w;
    ((float4*)out)[i] = r;
}

// ===========================================================================
// Unified prep: hi/lo splits, roundings, adj bit-pack. One launch.
// ===========================================================================
__global__ __launch_bounds__(256) void prep_kernel(const float* __restrict__ gcn,
                                                   const float* __restrict__ rel,
                                                   const float* __restrict__ W_Q,
                                                   const float* __restrict__ W_K,
                                                   const float* __restrict__ W_gcn,
                                                   const float* __restrict__ W_out,
                                                   const int* __restrict__ adj) {
    const int blk = blockIdx.x, t = threadIdx.x;
    if (blk < 2048) {
        const int i = blk * 256 + t;                 // float4 idx over [4096,512]
        const int row = i >> 7;
        const int c4 = (i & 127) * 4;
        float4 v = (c4 < 256)
            ? *(const float4*)(gcn + (size_t)row * 256 + c4)
            : *(const float4*)(rel + (size_t)row * 256 + c4 - 256);
        float4 hi, lo;
        hi.x = rna(v.x); lo.x = rna(v.x - hi.x);
        hi.y = rna(v.y); lo.y = rna(v.y - hi.y);
        hi.z = rna(v.z); lo.z = rna(v.z - hi.z);
        hi.w = rna(v.w); lo.w = rna(v.w - hi.w);
        ((float4*)g_inhi)[i] = hi;
        ((float4*)g_inlo)[i] = lo;
    } else if (blk < 2240) {
        const int i = (blk - 2048) * 256 + t;        // float4 idx
        const float* src; float* dhi; float* dlo; int j;
        if (i < 32768) { src = W_Q; dhi = g_wqhi; dlo = g_wqlo; j = i; }
        else           { src = W_K; dhi = g_wkhi; dlo = g_wklo; j = i - 32768; }
        float4 v = ((const float4*)src)[j];
        float4 hi, lo;
        hi.x = rna(v.x); lo.x = rna(v.x - hi.x);
        hi.y = rna(v.y); lo.y = rna(v.y - hi.y);
        hi.z = rna(v.z); lo.z = rna(v.z - hi.z);
        hi.w = rna(v.w); lo.w = rna(v.w - hi.w);
        ((float4*)dhi)[j] = hi;
        ((float4*)dlo)[j] = lo;
    } else if (blk < 3264) {
        const int i = (blk - 2240) * 256 + t;        // float4 idx
        const float* src; float* dst; int j;
        if (i < 131072) { src = W_gcn; dst = g_wgr; j = i; }
        else            { src = W_out; dst = g_wor; j = i - 131072; }
        float4 v = ((const float4*)src)[j];
        v.x = rna(v.x); v.y = rna(v.y); v.z = rna(v.z); v.w = rna(v.w);
        ((float4*)dst)[j] = v;
    } else {
        const int i = (blk - 3264) * 256 + t;        // int4 idx over 4M ints
        int4 v = ((const int4*)adj)[i];
        uint32_t nib = (uint32_t)(v.x != 0) | ((uint32_t)(v.y != 0) << 1) |
                       ((uint32_t)(v.z != 0) << 2) | ((uint32_t)(v.w != 0) << 3);
        uint32_t val = nib << ((i & 7) * 4);
        val |= __shfl_xor_sync(0xffffffffu, val, 1);
        val |= __shfl_xor_sync(0xffffffffu, val, 2);
        val |= __shfl_xor_sync(0xffffffffu, val, 4);
        if ((t & 7) == 0) g_adjbits[i >> 3] = val;
    }
}

// ===========================================================================
// Scores via 3xTF32 (hi/lo): grid (8 ntiles, 8 mtiles, 16 bh), 256 thr
// (unchanged from R10/R11 measured configuration)
// ===========================================================================
constexpr int SC_STR = 68;
constexpr int SC_TILE = 128 * SC_STR;
constexpr int SC_SMEM = 4 * SC_TILE * 4;

#define EPILOGUE_LOOP8(BODY)                                                  \
    do {                                                                      \
        const int lane = threadIdx.x & 31, wid = threadIdx.x >> 5;            \
        const int wm = (wid >> 1) * 32, wn = (wid & 1) * 64;                  \
        const int qr = lane >> 2, qk = lane & 3;                              \
        _Pragma("unroll")                                                     \
        for (int mi = 0; mi < 2; mi++)                                        \
            _Pragma("unroll")                                                 \
            for (int half = 0; half < 2; half++) {                            \
                const int row = wm + mi * 16 + qr + half * 8;                 \
                _Pragma("unroll")                                             \
                for (int ni = 0; ni < 8; ni++) {                              \
                    const int col = wn + ni * 8 + 2 * qk;                     \
                    float v0 = c[mi][ni][half * 2 + 0];                       \
                    float v1 = c[mi][ni][half * 2 + 1];                       \
                    BODY                                                      \
                }                                                             \
            }                                                                 \
    } while (0)

__global__ __launch_bounds__(256) void scores3_mma() {
    extern __shared__ uint32_t sm[];
    const int bh = blockIdx.z, b = bh >> 2, h = bh & 3;
    const int m0 = blockIdx.y * 128, n0 = blockIdx.x * 128;
    const int tid = threadIdx.x;
    const uint32_t sb = smem_u32(sm);

    const size_t qoff = ((size_t)(b * N_ + m0)) * D_ + h * 64;
    const size_t koff = ((size_t)(b * N_ + n0)) * D_ + h * 64;
    const float* srcs[4] = {g_qhi + qoff, g_qlo + qoff, g_khi + koff, g_klo + koff};
#pragma unroll
    for (int t = 0; t < 4; t++) {
        const uint32_t dst = sb + (uint32_t)(t * SC_TILE) * 4u;
        const float* s = srcs[t];
#pragma unroll
        for (int e = 0; e < 8; e++) {
            int idx = tid + 256 * e;
            int row = idx >> 4;
            int c4 = idx & 15;
            CP_A16(dst + (uint32_t)(row * SC_STR + c4 * 4) * 4u,
                   s + (size_t)row * D_ + c4 * 4);
        }
    }
    CP_COMMIT();
    CP_WAIT(0);
    __syncthreads();

    const uint32_t* sQh = sm;
    const uint32_t* sQl = sm + SC_TILE;
    const uint32_t* sKh = sm + 2 * SC_TILE;
    const uint32_t* sKl = sm + 3 * SC_TILE;

    const int lane = tid & 31, wid = tid >> 5;
    const int wm = (wid >> 1) * 32, wn = (wid & 1) * 64;
    const int qr = lane >> 2, qk = lane & 3;

    float c[2][8][4] = {};
#pragma unroll
    for (int kk = 0; kk < 8; kk++) {
        const int k0 = kk * 8;
        uint32_t ah[2][4], al[2][4];
#pragma unroll
        for (int mi = 0; mi < 2; mi++) {
            const int rb = wm + mi * 16 + qr;
            ah[mi][0] = sQh[(rb)     * SC_STR + k0 + qk];
            ah[mi][1] = sQh[(rb + 8) * SC_STR + k0 + qk];
            ah[mi][2] = sQh[(rb)     * SC_STR + k0 + qk + 4];
            ah[mi][3] = sQh[(rb + 8) * SC_STR + k0 + qk + 4];
            al[mi][0] = sQl[(rb)     * SC_STR + k0 + qk];
            al[mi][1] = sQl[(rb + 8) * SC_STR + k0 + qk];
            al[mi][2] = sQl[(rb)     * SC_STR + k0 + qk + 4];
            al[mi][3] = sQl[(rb + 8) * SC_STR + k0 + qk + 4];
        }
#pragma unroll
        for (int ni = 0; ni < 8; ni++) {
            const int nr = wn + ni * 8 + qr;
            uint32_t bh2[2], bl2[2];
            bh2[0] = sKh[nr * SC_STR + k0 + qk];
            bh2[1] = sKh[nr * SC_STR + k0 + qk + 4];
            bl2[0] = sKl[nr * SC_STR + k0 + qk];
            bl2[1] = sKl[nr * SC_STR + k0 + qk + 4];
#pragma unroll
            for (int mi = 0; mi < 2; mi++) {
                mma16n8k8(c[mi][ni], ah[mi], bh2);
                mma16n8k8(c[mi][ni], ah[mi], bl2);
                mma16n8k8(c[mi][ni], al[mi], bh2);
            }
        }
    }

    float* C = g_attn + (size_t)bh * N_ * N_ + (size_t)m0 * N_ + n0;
    EPILOGUE_LOOP8({
        *(float2*)(C + (size_t)row * N_ + col) = make_float2(v0, v1);
    });
}

// ---------------------------------------------------------------------------
// z-score attention — warp-per-row: 8 rows/block, pure shfl reductions,
// zero barriers / zero smem. lane handles 32 strided elements (coalesced f4).
// ---------------------------------------------------------------------------
__global__ __launch_bounds__(256) void zscore_kernel(const int* __restrict__ mask) {
    const int wid = threadIdx.x >> 5, lane = threadIdx.x & 31;
    const int row = (blockIdx.x << 3) + wid;
    const int i  = row & (N_ - 1);
    const int bh = row >> 10;
    const int b  = bh >> 2;
    float* sc = g_attn + (size_t)row * N_;
    const int* mrow = mask + (size_t)b * N_;
    // lane's full adj word (bits for elements [lane*32, lane*32+32) in row order)
    const uint32_t awf = g_adjbits[((size_t)b * N_ + i) * (N_ / 32) + lane];

    // load 32 elements per lane, coalesced: element j = c*128 + lane*4 + e
    float v[32];
    uint32_t mvb = 0;                 // valid-mask bit per element slot (c*4+e)
    float cnt = 0.f, s = 0.f, maxv = -1e30f;
#pragma unroll
    for (int cch = 0; cch < 8; cch++) {
        const float4 vv = ((const float4*)sc)[cch * 32 + lane];
        const int4  mm = ((const int4*)mrow)[cch * 32 + lane];
        const float vr[4] = {vv.x, vv.y, vv.z, vv.w};
        const int mr[4] = {mm.x == 0, mm.y == 0, mm.z == 0, mm.w == 0};
#pragma unroll
        for (int e = 0; e < 4; e++) {
            v[cch * 4 + e] = vr[e];
            if (mr[e]) {
                mvb |= (1u << (cch * 4 + e));
                cnt += 1.f; s += vr[e]; maxv = fmaxf(maxv, vr[e]);
            }
        }
    }
    // warp reduce (cnt, s, maxv)
#pragma unroll
    for (int o = 16; o > 0; o >>= 1) {
        cnt += __shfl_xor_sync(0xffffffffu, cnt, o);
        s   += __shfl_xor_sync(0xffffffffu, s, o);
        maxv = fmaxf(maxv, __shfl_xor_sync(0xffffffffu, maxv, o));
    }
    const float mean = s / (cnt + 1e-4f);          // exact div (matches ref)

    float ss = 0.f;
#pragma unroll
    for (int k = 0; k < 32; k++) {
        float d = v[k] - mean;
        if ((mvb >> k) & 1u) ss += d * d;
    }
#pragma unroll
    for (int o = 16; o > 0; o >>= 1) ss += __shfl_xor_sync(0xffffffffu, ss, o);
    const float stdv = sqrtf(ss / (cnt + 1e-4f) + 1e-10f);
    const float invstd = 1.f / (stdv + 1e-4f);     // sign(z)==sign(v-mean)

    // mx from maxv (monotone transform commutes with max); clamp reproduces
    // the all-thresholded edge (every weight killed anyway)
    float mx = (maxv - mean) * invstd;
    if (!(mx >= 0.f)) mx = -1e9f;

    // per element: exp, keep flags, partial sums
    float ev[32];
    uint32_t kb = 0;
    float se = 0.f, sk = 0.f;
#pragma unroll
    for (int cch = 0; cch < 8; cch++) {
        // adj word for this chunk lives in lane (cch*4 + lane>>3); bit (lane&7)*4+e
        const uint32_t aword = __shfl_sync(0xffffffffu, awf, cch * 4 + (lane >> 3));
#pragma unroll
        for (int e = 0; e < 4; e++) {
            const int k = cch * 4 + e;
            const int mvk = (mvb >> k) & 1;
            const float a = (float)((aword >> ((lane & 7) * 4 + e)) & 1u);
            float z = (v[k] - mean) * invstd;
            int ok = (mvk && z >= 0.f);
            float s2 = ok ? z : -1e9f;
            float ee = mvk ? (__expf(s2 - mx) * a) : 0.f;
            ee += 1e-10f;
            ev[k] = ee;
            se += ee;
            if (ok && a != 0.f) { kb |= (1u << k); sk += ee; }
        }
    }
#pragma unroll
    for (int o = 16; o > 0; o >>= 1) {
        se += __shfl_xor_sync(0xffffffffu, se, o);
        sk += __shfl_xor_sync(0xffffffffu, sk, o);
    }
    const float invse = 1.f / se;

#pragma unroll
    for (int cch = 0; cch < 8; cch++) {
        float4 w4;
        w4.x = ((kb >> (cch * 4 + 0)) & 1u) ? rna(ev[cch * 4 + 0] * invse) : 0.f;
        w4.y = ((kb >> (cch * 4 + 1)) & 1u) ? rna(ev[cch * 4 + 1] * invse) : 0.f;
        w4.z = ((kb >> (cch * 4 + 2)) & 1u) ? rna(ev[cch * 4 + 2] * invse) : 0.f;
        w4.w = ((kb >> (cch * 4 + 3)) & 1u) ? rna(ev[cch * 4 + 3] * invse) : 0.f;
        ((float4*)sc)[cch * 32 + lane] = w4;
    }

    if (lane == 0) g_denom[row] = sk * invse + 1.f;
}

// ===========================================================================
extern "C" void kernel_launch(void* const* d_in, const int* in_sizes, int n_in,
                              void* d_out, int out_size) {
    const float* gcn   = (const float*)d_in[0];
    const float* rel   = (const float*)d_in[1];
    const int*   adj   = (const int*)d_in[2];
    const int*   mask  = (const int*)d_in[3];
    const float* W_Q   = (const float*)d_in[4];
    const float* b_Q   = (const float*)d_in[5];
    const float* W_K   = (const float*)d_in[6];
    const float* b_K   = (const float*)d_in[7];
    const float* W_gcn = (const float*)d_in[8];
    const float* b_gcn = (const float*)d_in[9];
    const float* W_out = (const float*)d_in[10];
    const float* b_out = (const float*)d_in[11];
    float* out = (float*)d_out;

    cudaFuncSetAttribute(proj_mma,    cudaFuncAttributeMaxDynamicSharedMemorySize, MMA_SMEM);
    cudaFuncSetAttribute(axpx_mma,    cudaFuncAttributeMaxDynamicSharedMemorySize, MMA_SMEM);
    cudaFuncSetAttribute(tw_mma,      cudaFuncAttributeMaxDynamicSharedMemorySize, MMA_SMEM);
    cudaFuncSetAttribute(final_mma,   cudaFuncAttributeMaxDynamicSharedMemorySize, MMA_SMEM);
    cudaFuncSetAttribute(scores3_mma, cudaFuncAttributeMaxDynamicSharedMemorySize, SC_SMEM);

    // prep (hi/lo splits, roundings, adj pack) — one launch
    prep_kernel<<<7360, 256>>>(gcn, rel, W_Q, W_K, W_gcn, W_out, adj);

    // projections on tensor cores (fp32-accurate)
    proj_mma<<<dim3(32, 2), 256, MMA_SMEM>>>(b_Q, b_K);

    // scores + z-score attention
    scores3_mma<<<dim3(8, 8, 16), 256, SC_SMEM>>>();
    zscore_kernel<<<16 * N_ / 8, 256>>>(mask);

    // GCN layers
    for (int l = 0; l < L_; l++) {
        axpx_mma<<<dim3(8, 16), 256, MMA_SMEM>>>(gcn, l);
        tw_mma<<<dim3(8, 16), 256, MMA_SMEM>>>(b_gcn, l);
    }

    // output projection: split-K + deterministic reduce
    final_mma<<<dim3(4, 32), 256, MMA_SMEM>>>();
    reduce_final<<<1024, 256>>>(gcn, b_out, out);
}

// round 15
// speedup vs baseline: 1.3956x; 1.3956x over previous
#include <cuda_runtime.h>
#include <cstdint>
#include <math.h>

// Problem constants
constexpr int B_  = 4;
constexpr int N_  = 1024;
constexpr int D_  = 256;
constexpr int H_  = 4;
constexpr int L_  = 2;
constexpr int BN_ = B_ * N_;        // 4096
constexpr int FD_ = D_ * H_ * L_;   // 2048

// Scratch (static device globals)
__device__ float g_inhi[BN_ * 512];             // 8 MB  [gcn|rel] tf32-hi
__device__ float g_inlo[BN_ * 512];             // 8 MB  [gcn|rel] tf32-lo
__device__ float g_wqhi[512 * D_];
__device__ float g_wqlo[512 * D_];
__device__ float g_wkhi[D_ * D_];
__device__ float g_wklo[D_ * D_];
__device__ float g_qhi[BN_ * D_];
__device__ float g_qlo[BN_ * D_];
__device__ float g_khi[BN_ * D_];
__device__ float g_klo[BN_ * D_];
__device__ float g_attn[16 * N_ * N_];          // 64 MB
__device__ float g_denom[16 * N_];
__device__ float g_tmp[16 * N_ * D_];           // 16 MB
__device__ float g_final[BN_ * FD_];            // 32 MB
__device__ float g_part[4 * BN_ * D_];          // 16 MB
__device__ float g_wgr[8 * D_ * D_];            // rounded W_gcn
__device__ float g_wor[FD_ * D_];               // rounded W_out
__device__ uint32_t g_adjbits[B_ * N_ * (N_ / 32)];

// ===========================================================================
// helpers
// ===========================================================================
__device__ __forceinline__ uint32_t smem_u32(const void* p) {
    uint32_t a;
    asm("{ .reg .u64 t; cvta.to.shared.u64 t, %1; cvt.u32.u64 %0, t; }" : "=r"(a) : "l"(p));
    return a;
}
__device__ __forceinline__ uint32_t f2tf(float x) {
    uint32_t r;
    asm("cvt.rna.tf32.f32 %0, %1;" : "=r"(r) : "f"(x));
    return r;
}
__device__ __forceinline__ float rna(float x) { return __uint_as_float(f2tf(x)); }

__device__ __forceinline__ void mma16n8k8(float d[4], const uint32_t a[4],
                                          const uint32_t b[2]) {
    asm volatile(
        "mma.sync.aligned.m16n8k8.row.col.f32.tf32.tf32.f32 "
        "{%0,%1,%2,%3}, {%4,%5,%6,%7}, {%8,%9}, {%0,%1,%2,%3};"
        : "+f"(d[0]), "+f"(d[1]), "+f"(d[2]), "+f"(d[3])
        : "r"(a[0]), "r"(a[1]), "r"(a[2]), "r"(a[3]), "r"(b[0]), "r"(b[1]));
}

#define CP_A16(dst, src) \
    asm volatile("cp.async.cg.shared.global [%0], [%1], 16;" :: "r"(dst), "l"(src))
#define CP_COMMIT() asm volatile("cp.async.commit_group;")
#define CP_WAIT(n)  asm volatile("cp.async.wait_group %0;" :: "n"(n))

// ===========================================================================
// 512-thread pipelined tf32 mma core: block tile 128x256, K-chunk 32,
// 16 warps (4m x 4n), warp tile 32x64, 3-stage cp.async. Accumulates into c.
// (R11-measured configuration — 64x64 warp tile regressed in R12, reverted)
// ===========================================================================
constexpr int AS_STR = 36;
constexpr int BS_STR = 264;
constexpr int ASZ = 128 * AS_STR;          // 4608 words
constexpr int BSZ = 32 * BS_STR;           // 8448 words
constexpr int STG = ASZ + BSZ;             // 13056 words
constexpr int MMA_SMEM = 3 * STG * 4;      // 156672 B

__device__ __forceinline__ void mma_issue(const float* __restrict__ A, int lda,
                                          const float* __restrict__ B, int ldb,
                                          int kt, uint32_t sb) {
    const int tid = threadIdx.x;
    const uint32_t da = sb + (uint32_t)((kt % 3) * STG) * 4u;
    const uint32_t db = da + (uint32_t)ASZ * 4u;
    const float* Ak = A + kt * 32;
    const float* Bk = B + (size_t)(kt * 32) * ldb;
#pragma unroll
    for (int e = 0; e < 2; e++) {
        int idx = tid + 512 * e;
        int row = idx >> 3;
        int c4 = idx & 7;
        CP_A16(da + (uint32_t)(row * AS_STR + c4 * 4) * 4u,
               Ak + (size_t)row * lda + c4 * 4);
    }
#pragma unroll
    for (int e = 0; e < 4; e++) {
        int idx = tid + 512 * e;
        int kr = idx >> 6;
        int c4 = idx & 63;
        CP_A16(db + (uint32_t)(kr * BS_STR + c4 * 4) * 4u,
               Bk + (size_t)kr * ldb + c4 * 4);
    }
}

__device__ __forceinline__ void mma_core(const float* __restrict__ A, int lda,
                                         const float* __restrict__ B, int ldb,
                                         int K, float c[2][8][4], uint32_t* sm) {
    const int tid = threadIdx.x;
    const uint32_t sb = smem_u32(sm);
    const int lane = tid & 31, wid = tid >> 5;
    const int wm = (wid >> 2) * 32, wn = (wid & 3) * 64;
    const int qr = lane >> 2, qk = lane & 3;
    const int niter = K >> 5;

    mma_issue(A, lda, B, ldb, 0, sb); CP_COMMIT();
    mma_issue(A, lda, B, ldb, 1, sb); CP_COMMIT();

    for (int kt = 0; kt < niter; kt++) {
        if (kt + 2 < niter) mma_issue(A, lda, B, ldb, kt + 2, sb);
        CP_COMMIT();
        CP_WAIT(1);
        __syncthreads();
        const uint32_t* sA = sm + (kt % 3) * STG;
        const uint32_t* sB = sA + ASZ;
#pragma unroll
        for (int kk = 0; kk < 4; kk++) {
            const int k0 = kk * 8;
            uint32_t af[2][4];
#pragma unroll
            for (int mi = 0; mi < 2; mi++) {
                const int rb = wm + mi * 16 + qr;
                af[mi][0] = sA[(rb)     * AS_STR + k0 + qk];
                af[mi][1] = sA[(rb + 8) * AS_STR + k0 + qk];
                af[mi][2] = sA[(rb)     * AS_STR + k0 + qk + 4];
                af[mi][3] = sA[(rb + 8) * AS_STR + k0 + qk + 4];
            }
#pragma unroll
            for (int ni = 0; ni < 8; ni++) {
                uint32_t bf[2];
                bf[0] = sB[(k0 + qk)     * BS_STR + wn + ni * 8 + qr];
                bf[1] = sB[(k0 + qk + 4) * BS_STR + wn + ni * 8 + qr];
                mma16n8k8(c[0][ni], af[0], bf);
                mma16n8k8(c[1][ni], af[1], bf);
            }
        }
        __syncthreads();
    }
}

// Epilogue: row = wm+mi*16+qr+half*8, col = wn+ni*8+2qk (cols span 256)
#define EPILOGUE_LOOP(BODY)                                                   \
    do {                                                                      \
        const int lane = threadIdx.x & 31, wid = threadIdx.x >> 5;            \
        const int wm = (wid >> 2) * 32, wn = (wid & 3) * 64;                  \
        const int qr = lane >> 2, qk = lane & 3;                              \
        _Pragma("unroll")                                                     \
        for (int mi = 0; mi < 2; mi++)                                        \
            _Pragma("unroll")                                                 \
            for (int half = 0; half < 2; half++) {                            \
                const int row = wm + mi * 16 + qr + half * 8;                 \
                _Pragma("unroll")                                             \
                for (int ni = 0; ni < 8; ni++) {                              \
                    const int col = wn + ni * 8 + 2 * qk;                     \
                    float v0 = c[mi][ni][half * 2 + 0];                       \
                    float v1 = c[mi][ni][half * 2 + 1];                       \
                    BODY                                                      \
                }                                                             \
            }                                                                 \
    } while (0)

// ===========================================================================
// T[bh] = a[bh] @ X[b] + X[b]  (K=1024) -> g_tmp (rna-rounded)
// grid (8 mtiles, 16 bh), 512 thr
// ===========================================================================
__global__ __launch_bounds__(512) void axpx_mma(const float* __restrict__ gcn, int l) {
    extern __shared__ uint32_t sm[];
    const int bh = blockIdx.y, b = bh >> 2, h = bh & 3;
    const int m0 = blockIdx.x * 128;
    const float* A = g_attn + (size_t)bh * N_ * N_ + (size_t)m0 * N_;
    const float* Xg; const float* Xe; int ldg, lde;
    if (l == 0) {
        Xg = g_inhi + (size_t)b * N_ * 512; ldg = 512;     // hi(gcn) = cols 0..255
        Xe = gcn + (size_t)b * N_ * D_;     lde = D_;
    } else {
        Xg = g_final + (size_t)b * N_ * FD_ + 2 * h * D_; ldg = FD_;
        Xe = Xg; lde = FD_;
    }

    float c[2][8][4] = {};
    mma_core(A, N_, Xg, ldg, N_, c, sm);

    const float* Xa = Xe + (size_t)m0 * lde;
    float* C = g_tmp + (size_t)bh * N_ * D_ + (size_t)m0 * D_;
    EPILOGUE_LOOP({
        v0 = rna(v0 + Xa[(size_t)row * lde + col]);
        v1 = rna(v1 + Xa[(size_t)row * lde + col + 1]);
        *(float2*)(C + (size_t)row * D_ + col) = make_float2(v0, v1);
    });
}

// ===========================================================================
// g_final[:, idx*D:] = relu((T @ W_gcn[idx] + 2*b_gcn[idx]) / denom)  (rounded)
// grid (8 mtiles, 16 bh), K=256
// ===========================================================================
__global__ __launch_bounds__(512) void tw_mma(const float* __restrict__ bg, int l) {
    extern __shared__ uint32_t sm[];
    const int bh = blockIdx.y, b = bh >> 2, h = bh & 3;
    const int idx = h * L_ + l;
    const int m0 = blockIdx.x * 128;
    const float* A = g_tmp + (size_t)bh * N_ * D_ + (size_t)m0 * D_;
    const float* Bw = g_wgr + (size_t)idx * D_ * D_;

    float c[2][8][4] = {};
    mma_core(A, D_, Bw, D_, D_, c, sm);

    float* C = g_final + (size_t)b * N_ * FD_ + (size_t)idx * D_ + (size_t)m0 * FD_;
    const float* dn = g_denom + (size_t)bh * N_ + m0;
    const float* bgp = bg + (size_t)idx * D_;
    EPILOGUE_LOOP({
        const float inv = 1.f / dn[row];
        v0 = rna(fmaxf((v0 + 2.f * bgp[col])     * inv, 0.f));
        v1 = rna(fmaxf((v1 + 2.f * bgp[col + 1]) * inv, 0.f));
        *(float2*)(C + (size_t)row * FD_ + col) = make_float2(v0, v1);
    });
}

// ===========================================================================
// Projections on tensor cores (fp32-accurate via hi/lo 3-mma)
// grid (32 mtiles, 2): z=0 q (K=512), z=1 k (K=256)
// ===========================================================================
__global__ __launch_bounds__(512) void proj_mma(const float* __restrict__ b_Q,
                                                const float* __restrict__ b_K) {
    extern __shared__ uint32_t sm[];
    const int z = blockIdx.y;
    const int m0 = blockIdx.x * 128;
    const float* Ahi = g_inhi + (size_t)m0 * 512;
    const float* Alo = g_inlo + (size_t)m0 * 512;
    const float* Bhi = z ? g_wkhi : g_wqhi;
    const float* Blo = z ? g_wklo : g_wqlo;
    const int K = z ? 256 : 512;

    float c[2][8][4] = {};
    mma_core(Ahi, 512, Bhi, D_, K, c, sm);
    mma_core(Ahi, 512, Blo, D_, K, c, sm);
    mma_core(Alo, 512, Bhi, D_, K, c, sm);

    const float* bias = z ? b_K : b_Q;
    float* Chi = z ? g_khi : g_qhi;
    float* Clo = z ? g_klo : g_qlo;
    EPILOGUE_LOOP({
        float f0 = v0 + bias[col];
        float f1 = v1 + bias[col + 1];
        float h0 = rna(f0);
        float h1 = rna(f1);
        *(float2*)(Chi + (size_t)(m0 + row) * D_ + col) = make_float2(h0, h1);
        *(float2*)(Clo + (size_t)(m0 + row) * D_ + col) =
            make_float2(rna(f0 - h0), rna(f1 - h1));
    });
}

// ===========================================================================
// Split-K output GEMM + reduce
// ===========================================================================
__global__ __launch_bounds__(512) void final_mma() {
    extern __shared__ uint32_t sm[];
    const int kc = blockIdx.x, m0 = blockIdx.y * 128;
    const float* A = g_final + (size_t)m0 * FD_ + kc * 512;
    const float* Bw = g_wor + (size_t)kc * 512 * D_;

    float c[2][8][4] = {};
    mma_core(A, FD_, Bw, D_, 512, c, sm);

    float* C = g_part + (size_t)kc * BN_ * D_ + (size_t)m0 * D_;
    EPILOGUE_LOOP({
        *(float2*)(C + (size_t)row * D_ + col) = make_float2(v0, v1);
    });
}

__global__ __launch_bounds__(256) void reduce_final(const float* __restrict__ gcn,
                                                    const float* __restrict__ bo,
                                                    float* __restrict__ out) {
    const int i = blockIdx.x * 256 + threadIdx.x;
    const float4 p0 = ((const float4*)g_part)[i];
    const float4 p1 = ((const float4*)(g_part + (size_t)BN_ * D_))[i];
    const float4 p2 = ((const float4*)(g_part + (size_t)2 * BN_ * D_))[i];
    const float4 p3 = ((const float4*)(g_part + (size_t)3 * BN_ * D_))[i];
    const float4 g  = ((const float4*)gcn)[i];
    const float4 bb = ((const float4*)bo)[i & 63];
    float4 r;
    r.x = g.x + ((p0.x + p1.x) + (p2.x + p3.x)) + bb.x;
    r.y = g.y + ((p0.y + p1.y) + (p2.y + p3.y)) + bb.y;
    r.z = g.z + ((p0.z + p1.z) + (p2.z + p3.z)) + bb.z;
    r.w = g.w + ((p0.w + p1.w) + (p2.w + p3.w)) + bb.w;
    ((float4*)out)[i] = r;
}

// ===========================================================================
// Unified prep: hi/lo splits, roundings, adj bit-pack. One launch.
// blocks: [0,2048) in hi/lo | [2048,2240) W_Q/W_K hi/lo |
//         [2240,3264) W_gcn/W_out round | [3264,4288) adj pack (MLP=4)
// ===========================================================================
__global__ __launch_bounds__(256) void prep_kernel(const float* __restrict__ gcn,
                                                   const float* __restrict__ rel,
                                                   const float* __restrict__ W_Q,
                                                   const float* __restrict__ W_K,
                                                   const float* __restrict__ W_gcn,
                                                   const float* __restrict__ W_out,
                                                   const int* __restrict__ adj) {
    const int blk = blockIdx.x, t = threadIdx.x;
    if (blk < 2048) {
        const int i = blk * 256 + t;                 // float4 idx over [4096,512]
        const int row = i >> 7;
        const int c4 = (i & 127) * 4;
        float4 v = (c4 < 256)
            ? *(const float4*)(gcn + (size_t)row * 256 + c4)
            : *(const float4*)(rel + (size_t)row * 256 + c4 - 256);
        float4 hi, lo;
        hi.x = rna(v.x); lo.x = rna(v.x - hi.x);
        hi.y = rna(v.y); lo.y = rna(v.y - hi.y);
        hi.z = rna(v.z); lo.z = rna(v.z - hi.z);
        hi.w = rna(v.w); lo.w = rna(v.w - hi.w);
        ((float4*)g_inhi)[i] = hi;
        ((float4*)g_inlo)[i] = lo;
    } else if (blk < 2240) {
        const int i = (blk - 2048) * 256 + t;        // float4 idx
        const float* src; float* dhi; float* dlo; int j;
        if (i < 32768) { src = W_Q; dhi = g_wqhi; dlo = g_wqlo; j = i; }
        else           { src = W_K; dhi = g_wkhi; dlo = g_wklo; j = i - 32768; }
        float4 v = ((const float4*)src)[j];
        float4 hi, lo;
        hi.x = rna(v.x); lo.x = rna(v.x - hi.x);
        hi.y = rna(v.y); lo.y = rna(v.y - hi.y);
        hi.z = rna(v.z); lo.z = rna(v.z - hi.z);
        hi.w = rna(v.w); lo.w = rna(v.w - hi.w);
        ((float4*)dhi)[j] = hi;
        ((float4*)dlo)[j] = lo;
    } else if (blk < 3264) {
        const int i = (blk - 2240) * 256 + t;        // float4 idx
        const float* src; float* dst; int j;
        if (i < 131072) { src = W_gcn; dst = g_wgr; j = i; }
        else            { src = W_out; dst = g_wor; j = i - 131072; }
        float4 v = ((const float4*)src)[j];
        v.x = rna(v.x); v.y = rna(v.y); v.z = rna(v.z); v.w = rna(v.w);
        ((float4*)dst)[j] = v;
    } else {
        // adj pack, 4 int4 loads per thread (MLP=4; 64B contiguous/thread)
        const int i = (blk - 3264) * 256 + t;        // 16-int group idx (262144)
        const int4* src = (const int4*)adj + (size_t)i * 4;
        int4 w0 = src[0];
        int4 w1 = src[1];
        int4 w2 = src[2];
        int4 w3 = src[3];
        uint32_t bits =
            ((uint32_t)(w0.x != 0))       | ((uint32_t)(w0.y != 0) << 1)  |
            ((uint32_t)(w0.z != 0) << 2)  | ((uint32_t)(w0.w != 0) << 3)  |
            ((uint32_t)(w1.x != 0) << 4)  | ((uint32_t)(w1.y != 0) << 5)  |
            ((uint32_t)(w1.z != 0) << 6)  | ((uint32_t)(w1.w != 0) << 7)  |
            ((uint32_t)(w2.x != 0) << 8)  | ((uint32_t)(w2.y != 0) << 9)  |
            ((uint32_t)(w2.z != 0) << 10) | ((uint32_t)(w2.w != 0) << 11) |
            ((uint32_t)(w3.x != 0) << 12) | ((uint32_t)(w3.y != 0) << 13) |
            ((uint32_t)(w3.z != 0) << 14) | ((uint32_t)(w3.w != 0) << 15);
        uint32_t val = bits << ((i & 1) * 16);
        val |= __shfl_xor_sync(0xffffffffu, val, 1);
        if ((t & 1) == 0) g_adjbits[i >> 1] = val;
    }
}

// ===========================================================================
// Scores via 3xTF32 (hi/lo): grid (8 ntiles, 8 mtiles, 16 bh), 256 thr
// ===========================================================================
constexpr int SC_STR = 68;
constexpr int SC_TILE = 128 * SC_STR;
constexpr int SC_SMEM = 4 * SC_TILE * 4;

#define EPILOGUE_LOOP8(BODY)                                                  \
    do {                                                                      \
        const int lane = threadIdx.x & 31, wid = threadIdx.x >> 5;            \
        const int wm = (wid >> 1) * 32, wn = (wid & 1) * 64;                  \
        const int qr = lane >> 2, qk = lane & 3;                              \
        _Pragma("unroll")                                                     \
        for (int mi = 0; mi < 2; mi++)                                        \
            _Pragma("unroll")                                                 \
            for (int half = 0; half < 2; half++) {                            \
                const int row = wm + mi * 16 + qr + half * 8;                 \
                _Pragma("unroll")                                             \
                for (int ni = 0; ni < 8; ni++) {                              \
                    const int col = wn + ni * 8 + 2 * qk;                     \
                    float v0 = c[mi][ni][half * 2 + 0];                       \
                    float v1 = c[mi][ni][half * 2 + 1];                       \
                    BODY                                                      \
                }                                                             \
            }                                                                 \
    } while (0)

__global__ __launch_bounds__(256) void scores3_mma() {
    extern __shared__ uint32_t sm[];
    const int bh = blockIdx.z, b = bh >> 2, h = bh & 3;
    const int m0 = blockIdx.y * 128, n0 = blockIdx.x * 128;
    const int tid = threadIdx.x;
    const uint32_t sb = smem_u32(sm);

    const size_t qoff = ((size_t)(b * N_ + m0)) * D_ + h * 64;
    const size_t koff = ((size_t)(b * N_ + n0)) * D_ + h * 64;
    const float* srcs[4] = {g_qhi + qoff, g_qlo + qoff, g_khi + koff, g_klo + koff};
#pragma unroll
    for (int t = 0; t < 4; t++) {
        const uint32_t dst = sb + (uint32_t)(t * SC_TILE) * 4u;
        const float* s = srcs[t];
#pragma unroll
        for (int e = 0; e < 8; e++) {
            int idx = tid + 256 * e;
            int row = idx >> 4;
            int c4 = idx & 15;
            CP_A16(dst + (uint32_t)(row * SC_STR + c4 * 4) * 4u,
                   s + (size_t)row * D_ + c4 * 4);
        }
    }
    CP_COMMIT();
    CP_WAIT(0);
    __syncthreads();

    const uint32_t* sQh = sm;
    const uint32_t* sQl = sm + SC_TILE;
    const uint32_t* sKh = sm + 2 * SC_TILE;
    const uint32_t* sKl = sm + 3 * SC_TILE;

    const int lane = tid & 31, wid = tid >> 5;
    const int wm = (wid >> 1) * 32, wn = (wid & 1) * 64;
    const int qr = lane >> 2, qk = lane & 3;

    float c[2][8][4] = {};
#pragma unroll
    for (int kk = 0; kk < 8; kk++) {
        const int k0 = kk * 8;
        uint32_t ah[2][4], al[2][4];
#pragma unroll
        for (int mi = 0; mi < 2; mi++) {
            const int rb = wm + mi * 16 + qr;
            ah[mi][0] = sQh[(rb)     * SC_STR + k0 + qk];
            ah[mi][1] = sQh[(rb + 8) * SC_STR + k0 + qk];
            ah[mi][2] = sQh[(rb)     * SC_STR + k0 + qk + 4];
            ah[mi][3] = sQh[(rb + 8) * SC_STR + k0 + qk + 4];
            al[mi][0] = sQl[(rb)     * SC_STR + k0 + qk];
            al[mi][1] = sQl[(rb + 8) * SC_STR + k0 + qk];
            al[mi][2] = sQl[(rb)     * SC_STR + k0 + qk + 4];
            al[mi][3] = sQl[(rb + 8) * SC_STR + k0 + qk + 4];
        }
#pragma unroll
        for (int ni = 0; ni < 8; ni++) {
            const int nr = wn + ni * 8 + qr;
            uint32_t bh2[2], bl2[2];
            bh2[0] = sKh[nr * SC_STR + k0 + qk];
            bh2[1] = sKh[nr * SC_STR + k0 + qk + 4];
            bl2[0] = sKl[nr * SC_STR + k0 + qk];
            bl2[1] = sKl[nr * SC_STR + k0 + qk + 4];
#pragma unroll
            for (int mi = 0; mi < 2; mi++) {
                mma16n8k8(c[mi][ni], ah[mi], bh2);
                mma16n8k8(c[mi][ni], ah[mi], bl2);
                mma16n8k8(c[mi][ni], al[mi], bh2);
            }
        }
    }

    float* C = g_attn + (size_t)bh * N_ * N_ + (size_t)m0 * N_ + n0;
    EPILOGUE_LOOP8({
        *(float2*)(C + (size_t)row * N_ + col) = make_float2(v0, v1);
    });
}

// ---------------------------------------------------------------------------
// z-score attention — vectorized + merged reductions (R11-measured version)
// ---------------------------------------------------------------------------
__device__ __forceinline__ void blockReduce3(float& a, float& b, float& m,
                                             float* sbuf) {
    const int tid = threadIdx.x;
#pragma unroll
    for (int o = 16; o > 0; o >>= 1) {
        a += __shfl_xor_sync(0xffffffffu, a, o);
        b += __shfl_xor_sync(0xffffffffu, b, o);
        m = fmaxf(m, __shfl_xor_sync(0xffffffffu, m, o));
    }
    if ((tid & 31) == 0) {
        int w = tid >> 5;
        sbuf[w] = a; sbuf[8 + w] = b; sbuf[16 + w] = m;
    }
    __syncthreads();
    if (tid < 8) {
        float aa = sbuf[tid], bb = sbuf[8 + tid], mm = sbuf[16 + tid];
#pragma unroll
        for (int o = 4; o > 0; o >>= 1) {
            aa += __shfl_xor_sync(0xffu, aa, o);
            bb += __shfl_xor_sync(0xffu, bb, o);
            mm = fmaxf(mm, __shfl_xor_sync(0xffu, mm, o));
        }
        if (tid == 0) { sbuf[0] = aa; sbuf[8] = bb; sbuf[16] = mm; }
    }
    __syncthreads();
    a = sbuf[0]; b = sbuf[8]; m = sbuf[16];
    __syncthreads();
}

__device__ __forceinline__ void blockReduce2(float& a, float& b, float* sbuf) {
    const int tid = threadIdx.x;
#pragma unroll
    for (int o = 16; o > 0; o >>= 1) {
        a += __shfl_xor_sync(0xffffffffu, a, o);
        b += __shfl_xor_sync(0xffffffffu, b, o);
    }
    if ((tid & 31) == 0) {
        int w = tid >> 5;
        sbuf[w] = a; sbuf[8 + w] = b;
    }
    __syncthreads();
    if (tid < 8) {
        float aa = sbuf[tid], bb = sbuf[8 + tid];
#pragma unroll
        for (int o = 4; o > 0; o >>= 1) {
            aa += __shfl_xor_sync(0xffu, aa, o);
            bb += __shfl_xor_sync(0xffu, bb, o);
        }
        if (tid == 0) { sbuf[0] = aa; sbuf[8] = bb; }
    }
    __syncthreads();
    a = sbuf[0]; b = sbuf[8];
    __syncthreads();
}

__device__ __forceinline__ float blockReduce1(float v, float* sbuf) {
    const int tid = threadIdx.x;
#pragma unroll
    for (int o = 16; o > 0; o >>= 1) v += __shfl_xor_sync(0xffffffffu, v, o);
    if ((tid & 31) == 0) sbuf[tid >> 5] = v;
    __syncthreads();
    if (tid < 8) {
        v = sbuf[tid];
#pragma unroll
        for (int o = 4; o > 0; o >>= 1) v += __shfl_xor_sync(0xffu, v, o);
        if (tid == 0) sbuf[0] = v;
    }
    __syncthreads();
    float r = sbuf[0];
    __syncthreads();
    return r;
}

__global__ __launch_bounds__(256) void zscore_kernel(const int* __restrict__ mask) {
    const int row = blockIdx.x;
    const int i  = row & (N_ - 1);
    const int bh = row >> 10;
    const int b  = bh >> 2;
    float* sc = g_attn + (size_t)row * N_;
    const uint32_t* abits = g_adjbits + ((size_t)b * N_ + i) * (N_ / 32);
    const int* mrow = mask + (size_t)b * N_;
    const int tid = threadIdx.x;
    __shared__ float sbuf[24];

    // vector loads: 4 consecutive elements per thread
    const float4 v4 = ((const float4*)sc)[tid];
    const int4  m4 = ((const int4*)mrow)[tid];
    const uint32_t aw = abits[tid >> 3];
    const int bitbase = (tid & 7) * 4;

    float v[4] = {v4.x, v4.y, v4.z, v4.w};
    const int mvi[4] = {m4.x == 0, m4.y == 0, m4.z == 0, m4.w == 0};
    float av[4];
#pragma unroll
    for (int e = 0; e < 4; e++) av[e] = (float)((aw >> (bitbase + e)) & 1u);

    // pass 1: cnt, sum, masked max (z monotone in v -> mx derivable from maxv)
    float cnt = 0.f, s = 0.f, maxv = -1e30f;
#pragma unroll
    for (int e = 0; e < 4; e++) {
        if (mvi[e]) { cnt += 1.f; s += v[e]; maxv = fmaxf(maxv, v[e]); }
    }
    blockReduce3(cnt, s, maxv, sbuf);
    const float mean = s / (cnt + 1e-4f);          // exact div (matches ref)

    // pass 2: sum of squared deviations
    float ss = 0.f;
#pragma unroll
    for (int e = 0; e < 4; e++) {
        float d = v[e] - mean;
        if (mvi[e]) ss += d * d;
    }
    ss = blockReduce1(ss, sbuf);
    const float stdv = sqrtf(ss / (cnt + 1e-4f) + 1e-10f);
    const float invstd = 1.f / (stdv + 1e-4f);     // sign(z)==sign(v-mean)

    // mx from maxv: monotone transform commutes with max; clamp reproduces
    // the all-thresholded edge (where every weight is killed anyway)
    float mx = (maxv - mean) * invstd;
    if (!(mx >= 0.f)) mx = -1e9f;

    float s2[4];
    int keep[4];
#pragma unroll
    for (int e = 0; e < 4; e++) {
        float z = (v[e] - mean) * invstd;
        int ok = (mvi[e] && z >= 0.f);
        s2[e] = ok ? z : -1e9f;
        keep[e] = (ok && av[e] != 0.f);
    }

    // pass 3: se and kept-sum together
    float ev[4], se = 0.f, sk = 0.f;
#pragma unroll
    for (int e = 0; e < 4; e++) {
        float ee = mvi[e] ? (__expf(s2[e] - mx) * av[e]) : 0.f;
        ee += 1e-10f;
        ev[e] = ee;
        se += ee;
        if (keep[e]) sk += ee;
    }
    blockReduce2(se, sk, sbuf);
    const float invse = 1.f / se;

    float4 w4;
    w4.x = keep[0] ? rna(ev[0] * invse) : 0.f;
    w4.y = keep[1] ? rna(ev[1] * invse) : 0.f;
    w4.z = keep[2] ? rna(ev[2] * invse) : 0.f;
    w4.w = keep[3] ? rna(ev[3] * invse) : 0.f;
    ((float4*)sc)[tid] = w4;

    if (tid == 0) g_denom[row] = sk * invse + 1.f;
}

// ===========================================================================
extern "C" void kernel_launch(void* const* d_in, const int* in_sizes, int n_in,
                              void* d_out, int out_size) {
    const float* gcn   = (const float*)d_in[0];
    const float* rel   = (const float*)d_in[1];
    const int*   adj   = (const int*)d_in[2];
    const int*   mask  = (const int*)d_in[3];
    const float* W_Q   = (const float*)d_in[4];
    const float* b_Q   = (const float*)d_in[5];
    const float* W_K   = (const float*)d_in[6];
    const float* b_K   = (const float*)d_in[7];
    const float* W_gcn = (const float*)d_in[8];
    const float* b_gcn = (const float*)d_in[9];
    const float* W_out = (const float*)d_in[10];
    const float* b_out = (const float*)d_in[11];
    float* out = (float*)d_out;

    cudaFuncSetAttribute(proj_mma,    cudaFuncAttributeMaxDynamicSharedMemorySize, MMA_SMEM);
    cudaFuncSetAttribute(axpx_mma,    cudaFuncAttributeMaxDynamicSharedMemorySize, MMA_SMEM);
    cudaFuncSetAttribute(tw_mma,      cudaFuncAttributeMaxDynamicSharedMemorySize, MMA_SMEM);
    cudaFuncSetAttribute(final_mma,   cudaFuncAttributeMaxDynamicSharedMemorySize, MMA_SMEM);
    cudaFuncSetAttribute(scores3_mma, cudaFuncAttributeMaxDynamicSharedMemorySize, SC_SMEM);

    // prep (hi/lo splits, roundings, adj pack) — one launch
    prep_kernel<<<4288, 256>>>(gcn, rel, W_Q, W_K, W_gcn, W_out, adj);

    // projections on tensor cores (fp32-accurate)
    proj_mma<<<dim3(32, 2), 512, MMA_SMEM>>>(b_Q, b_K);

    // scores + z-score attention
    scores3_mma<<<dim3(8, 8, 16), 256, SC_SMEM>>>();
    zscore_kernel<<<16 * N_, 256>>>(mask);

    // GCN layers
    for (int l = 0; l < L_; l++) {
        axpx_mma<<<dim3(8, 16), 512, MMA_SMEM>>>(gcn, l);
        tw_mma<<<dim3(8, 16), 512, MMA_SMEM>>>(b_gcn, l);
    }

    // output projection: split-K + deterministic reduce
    final_mma<<<dim3(4, 32), 512, MMA_SMEM>>>();
    reduce_final<<<1024, 256>>>(gcn, b_out, out);
}

// round 17
// speedup vs baseline: 1.4280x; 1.0232x over previous
#include <cuda_runtime.h>
#include <cstdint>
#include <math.h>

// Problem constants
constexpr int B_  = 4;
constexpr int N_  = 1024;
constexpr int D_  = 256;
constexpr int H_  = 4;
constexpr int L_  = 2;
constexpr int BN_ = B_ * N_;        // 4096
constexpr int FD_ = D_ * H_ * L_;   // 2048

// Scratch (static device globals)
__device__ float g_inhi[BN_ * 512];             // 8 MB  [gcn|rel] tf32-hi
__device__ float g_inlo[BN_ * 512];             // 8 MB  [gcn|rel] tf32-lo
__device__ float g_wqhi[512 * D_];
__device__ float g_wqlo[512 * D_];
__device__ float g_wkhi[D_ * D_];
__device__ float g_wklo[D_ * D_];
__device__ float g_qhi[BN_ * D_];
__device__ float g_qlo[BN_ * D_];
__device__ float g_khi[BN_ * D_];
__device__ float g_klo[BN_ * D_];
__device__ float g_attn[16 * N_ * N_];          // 64 MB
__device__ float g_denom[16 * N_];
__device__ float g_tmp[16 * N_ * D_];           // 16 MB
__device__ float g_final[BN_ * FD_];            // 32 MB
__device__ float g_part[4 * BN_ * D_];          // 16 MB
__device__ float g_wgr[8 * D_ * D_];            // rounded W_gcn
__device__ float g_wor[FD_ * D_];               // rounded W_out
__device__ uint32_t g_adjbits[B_ * N_ * (N_ / 32)];

// ===========================================================================
// helpers
// ===========================================================================
__device__ __forceinline__ uint32_t smem_u32(const void* p) {
    uint32_t a;
    asm("{ .reg .u64 t; cvta.to.shared.u64 t, %1; cvt.u32.u64 %0, t; }" : "=r"(a) : "l"(p));
    return a;
}
__device__ __forceinline__ uint32_t f2tf(float x) {
    uint32_t r;
    asm("cvt.rna.tf32.f32 %0, %1;" : "=r"(r) : "f"(x));
    return r;
}
__device__ __forceinline__ float rna(float x) { return __uint_as_float(f2tf(x)); }

__device__ __forceinline__ void mma16n8k8(float d[4], const uint32_t a[4],
                                          const uint32_t b[2]) {
    asm volatile(
        "mma.sync.aligned.m16n8k8.row.col.f32.tf32.tf32.f32 "
        "{%0,%1,%2,%3}, {%4,%5,%6,%7}, {%8,%9}, {%0,%1,%2,%3};"
        : "+f"(d[0]), "+f"(d[1]), "+f"(d[2]), "+f"(d[3])
        : "r"(a[0]), "r"(a[1]), "r"(a[2]), "r"(a[3]), "r"(b[0]), "r"(b[1]));
}

#define CP_A16(dst, src) \
    asm volatile("cp.async.cg.shared.global [%0], [%1], 16;" :: "r"(dst), "l"(src))
#define CP_COMMIT() asm volatile("cp.async.commit_group;")
#define CP_WAIT(n)  asm volatile("cp.async.wait_group %0;" :: "n"(n))

// ===========================================================================
// 512-thread pipelined tf32 mma core: block tile 128x256, K-chunk 32,
// 16 warps (4m x 4n), warp tile 32x64, 4-stage cp.async. Accumulates into c.
// ===========================================================================
constexpr int AS_STR = 36;
constexpr int BS_STR = 264;
constexpr int ASZ = 128 * AS_STR;          // 4608 words
constexpr int BSZ = 32 * BS_STR;           // 8448 words
constexpr int STG = ASZ + BSZ;             // 13056 words
constexpr int MMA_SMEM = 4 * STG * 4;      // 208896 B (4-stage)

__device__ __forceinline__ void mma_issue(const float* __restrict__ A, int lda,
                                          const float* __restrict__ B, int ldb,
                                          int kt, uint32_t sb) {
    const int tid = threadIdx.x;
    const uint32_t da = sb + (uint32_t)((kt & 3) * STG) * 4u;
    const uint32_t db = da + (uint32_t)ASZ * 4u;
    const float* Ak = A + kt * 32;
    const float* Bk = B + (size_t)(kt * 32) * ldb;
#pragma unroll
    for (int e = 0; e < 2; e++) {
        int idx = tid + 512 * e;
        int row = idx >> 3;
        int c4 = idx & 7;
        CP_A16(da + (uint32_t)(row * AS_STR + c4 * 4) * 4u,
               Ak + (size_t)row * lda + c4 * 4);
    }
#pragma unroll
    for (int e = 0; e < 4; e++) {
        int idx = tid + 512 * e;
        int kr = idx >> 6;
        int c4 = idx & 63;
        CP_A16(db + (uint32_t)(kr * BS_STR + c4 * 4) * 4u,
               Bk + (size_t)kr * ldb + c4 * 4);
    }
}

__device__ __forceinline__ void mma_core(const float* __restrict__ A, int lda,
                                         const float* __restrict__ B, int ldb,
                                         int K, float c[2][8][4], uint32_t* sm) {
    const int tid = threadIdx.x;
    const uint32_t sb = smem_u32(sm);
    const int lane = tid & 31, wid = tid >> 5;
    const int wm = (wid >> 2) * 32, wn = (wid & 3) * 64;
    const int qr = lane >> 2, qk = lane & 3;
    const int niter = K >> 5;

    mma_issue(A, lda, B, ldb, 0, sb); CP_COMMIT();
    mma_issue(A, lda, B, ldb, 1, sb); CP_COMMIT();
    if (niter > 2) mma_issue(A, lda, B, ldb, 2, sb);
    CP_COMMIT();

    for (int kt = 0; kt < niter; kt++) {
        if (kt + 3 < niter) mma_issue(A, lda, B, ldb, kt + 3, sb);
        CP_COMMIT();
        CP_WAIT(3);               // stages kt..kt+2 may be in flight; kt done
        __syncthreads();
        const uint32_t* sA = sm + (kt & 3) * STG;
        const uint32_t* sB = sA + ASZ;
#pragma unroll
        for (int kk = 0; kk < 4; kk++) {
            const int k0 = kk * 8;
            uint32_t af[2][4];
#pragma unroll
            for (int mi = 0; mi < 2; mi++) {
                const int rb = wm + mi * 16 + qr;
                af[mi][0] = sA[(rb)     * AS_STR + k0 + qk];
                af[mi][1] = sA[(rb + 8) * AS_STR + k0 + qk];
                af[mi][2] = sA[(rb)     * AS_STR + k0 + qk + 4];
                af[mi][3] = sA[(rb + 8) * AS_STR + k0 + qk + 4];
            }
#pragma unroll
            for (int ni = 0; ni < 8; ni++) {
                uint32_t bf[2];
                bf[0] = sB[(k0 + qk)     * BS_STR + wn + ni * 8 + qr];
                bf[1] = sB[(k0 + qk + 4) * BS_STR + wn + ni * 8 + qr];
                mma16n8k8(c[0][ni], af[0], bf);
                mma16n8k8(c[1][ni], af[1], bf);
            }
        }
        __syncthreads();
    }
}

// Epilogue: row = wm+mi*16+qr+half*8, col = wn+ni*8+2qk (cols span 256)
#define EPILOGUE_LOOP(BODY)                                                   \
    do {                                                                      \
        const int lane = threadIdx.x & 31, wid = threadIdx.x >> 5;            \
        const int wm = (wid >> 2) * 32, wn = (wid & 3) * 64;                  \
        const int qr = lane >> 2, qk = lane & 3;                              \
        _Pragma("unroll")                                                     \
        for (int mi = 0; mi < 2; mi++)                                        \
            _Pragma("unroll")                                                 \
            for (int half = 0; half < 2; half++) {                            \
                const int row = wm + mi * 16 + qr + half * 8;                 \
                _Pragma("unroll")                                             \
                for (int ni = 0; ni < 8; ni++) {                              \
                    const int col = wn + ni * 8 + 2 * qk;                     \
                    float v0 = c[mi][ni][half * 2 + 0];                       \
                    float v1 = c[mi][ni][half * 2 + 1];                       \
                    BODY                                                      \
                }                                                             \
            }                                                                 \
    } while (0)

// ===========================================================================
// T[bh] = a[bh] @ X[b] + X[b]  (K=1024) -> g_tmp (rna-rounded)
// grid (8 mtiles, 16 bh), 512 thr
// ===========================================================================
__global__ __launch_bounds__(512) void axpx_mma(const float* __restrict__ gcn, int l) {
    extern __shared__ uint32_t sm[];
    const int bh = blockIdx.y, b = bh >> 2, h = bh & 3;
    const int m0 = blockIdx.x * 128;
    const float* A = g_attn + (size_t)bh * N_ * N_ + (size_t)m0 * N_;
    const float* Xg; const float* Xe; int ldg, lde;
    if (l == 0) {
        Xg = g_inhi + (size_t)b * N_ * 512; ldg = 512;     // hi(gcn) = cols 0..255
        Xe = gcn + (size_t)b * N_ * D_;     lde = D_;
    } else {
        Xg = g_final + (size_t)b * N_ * FD_ + 2 * h * D_; ldg = FD_;
        Xe = Xg; lde = FD_;
    }

    float c[2][8][4] = {};
    mma_core(A, N_, Xg, ldg, N_, c, sm);

    const float* Xa = Xe + (size_t)m0 * lde;
    float* C = g_tmp + (size_t)bh * N_ * D_ + (size_t)m0 * D_;
    EPILOGUE_LOOP({
        v0 = rna(v0 + Xa[(size_t)row * lde + col]);
        v1 = rna(v1 + Xa[(size_t)row * lde + col + 1]);
        *(float2*)(C + (size_t)row * D_ + col) = make_float2(v0, v1);
    });
}

// ===========================================================================
// g_final[:, idx*D:] = relu((T @ W_gcn[idx] + 2*b_gcn[idx]) / denom)  (rounded)
// grid (8 mtiles, 16 bh), K=256
// ===========================================================================
__global__ __launch_bounds__(512) void tw_mma(const float* __restrict__ bg, int l) {
    extern __shared__ uint32_t sm[];
    const int bh = blockIdx.y, b = bh >> 2, h = bh & 3;
    const int idx = h * L_ + l;
    const int m0 = blockIdx.x * 128;
    const float* A = g_tmp + (size_t)bh * N_ * D_ + (size_t)m0 * D_;
    const float* Bw = g_wgr + (size_t)idx * D_ * D_;

    float c[2][8][4] = {};
    mma_core(A, D_, Bw, D_, D_, c, sm);

    float* C = g_final + (size_t)b * N_ * FD_ + (size_t)idx * D_ + (size_t)m0 * FD_;
    const float* dn = g_denom + (size_t)bh * N_ + m0;
    const float* bgp = bg + (size_t)idx * D_;
    EPILOGUE_LOOP({
        const float inv = 1.f / dn[row];
        v0 = rna(fmaxf((v0 + 2.f * bgp[col])     * inv, 0.f));
        v1 = rna(fmaxf((v1 + 2.f * bgp[col + 1]) * inv, 0.f));
        *(float2*)(C + (size_t)row * FD_ + col) = make_float2(v0, v1);
    });
}

// ===========================================================================
// Projections on tensor cores (fp32-accurate via hi/lo 3-mma)
// grid (32 mtiles, 2): z=0 q (K=512), z=1 k (K=256)
// ===========================================================================
__global__ __launch_bounds__(512) void proj_mma(const float* __restrict__ b_Q,
                                                const float* __restrict__ b_K) {
    extern __shared__ uint32_t sm[];
    const int z = blockIdx.y;
    const int m0 = blockIdx.x * 128;
    const float* Ahi = g_inhi + (size_t)m0 * 512;
    const float* Alo = g_inlo + (size_t)m0 * 512;
    const float* Bhi = z ? g_wkhi : g_wqhi;
    const float* Blo = z ? g_wklo : g_wqlo;
    const int K = z ? 256 : 512;

    float c[2][8][4] = {};
    mma_core(Ahi, 512, Bhi, D_, K, c, sm);
    mma_core(Ahi, 512, Blo, D_, K, c, sm);
    mma_core(Alo, 512, Bhi, D_, K, c, sm);

    const float* bias = z ? b_K : b_Q;
    float* Chi = z ? g_khi : g_qhi;
    float* Clo = z ? g_klo : g_qlo;
    EPILOGUE_LOOP({
        float f0 = v0 + bias[col];
        float f1 = v1 + bias[col + 1];
        float h0 = rna(f0);
        float h1 = rna(f1);
        *(float2*)(Chi + (size_t)(m0 + row) * D_ + col) = make_float2(h0, h1);
        *(float2*)(Clo + (size_t)(m0 + row) * D_ + col) =
            make_float2(rna(f0 - h0), rna(f1 - h1));
    });
}

// ===========================================================================
// Split-K output GEMM + reduce
// ===========================================================================
__global__ __launch_bounds__(512) void final_mma() {
    extern __shared__ uint32_t sm[];
    const int kc = blockIdx.x, m0 = blockIdx.y * 128;
    const float* A = g_final + (size_t)m0 * FD_ + kc * 512;
    const float* Bw = g_wor + (size_t)kc * 512 * D_;

    float c[2][8][4] = {};
    mma_core(A, FD_, Bw, D_, 512, c, sm);

    float* C = g_part + (size_t)kc * BN_ * D_ + (size_t)m0 * D_;
    EPILOGUE_LOOP({
        *(float2*)(C + (size_t)row * D_ + col) = make_float2(v0, v1);
    });
}

__global__ __launch_bounds__(256) void reduce_final(const float* __restrict__ gcn,
                                                    const float* __restrict__ bo,
                                                    float* __restrict__ out) {
    const int i = blockIdx.x * 256 + threadIdx.x;
    const float4 p0 = ((const float4*)g_part)[i];
    const float4 p1 = ((const float4*)(g_part + (size_t)BN_ * D_))[i];
    const float4 p2 = ((const float4*)(g_part + (size_t)2 * BN_ * D_))[i];
    const float4 p3 = ((const float4*)(g_part + (size_t)3 * BN_ * D_))[i];
    const float4 g  = ((const float4*)gcn)[i];
    const float4 bb = ((const float4*)bo)[i & 63];
    float4 r;
    r.x = g.x + ((p0.x + p1.x) + (p2.x + p3.x)) + bb.x;
    r.y = g.y + ((p0.y + p1.y) + (p2.y + p3.y)) + bb.y;
    r.z = g.z + ((p0.z + p1.z) + (p2.z + p3.z)) + bb.z;
    r.w = g.w + ((p0.w + p1.w) + (p2.w + p3.w)) + bb.w;
    ((float4*)out)[i] = r;
}

// ===========================================================================
// Unified prep: hi/lo splits, roundings, adj bit-pack (MLP=4). One launch.
// ===========================================================================
__global__ __launch_bounds__(256) void prep_kernel(const float* __restrict__ gcn,
                                                   const float* __restrict__ rel,
                                                   const float* __restrict__ W_Q,
                                                   const float* __restrict__ W_K,
                                                   const float* __restrict__ W_gcn,
                                                   const float* __restrict__ W_out,
                                                   const int* __restrict__ adj) {
    const int blk = blockIdx.x, t = threadIdx.x;
    if (blk < 2048) {
        const int i = blk * 256 + t;                 // float4 idx over [4096,512]
        const int row = i >> 7;
        const int c4 = (i & 127) * 4;
        float4 v = (c4 < 256)
            ? *(const float4*)(gcn + (size_t)row * 256 + c4)
            : *(const float4*)(rel + (size_t)row * 256 + c4 - 256);
        float4 hi, lo;
        hi.x = rna(v.x); lo.x = rna(v.x - hi.x);
        hi.y = rna(v.y); lo.y = rna(v.y - hi.y);
        hi.z = rna(v.z); lo.z = rna(v.z - hi.z);
        hi.w = rna(v.w); lo.w = rna(v.w - hi.w);
        ((float4*)g_inhi)[i] = hi;
        ((float4*)g_inlo)[i] = lo;
    } else if (blk < 2240) {
        const int i = (blk - 2048) * 256 + t;        // float4 idx
        const float* src; float* dhi; float* dlo; int j;
        if (i < 32768) { src = W_Q; dhi = g_wqhi; dlo = g_wqlo; j = i; }
        else           { src = W_K; dhi = g_wkhi; dlo = g_wklo; j = i - 32768; }
        float4 v = ((const float4*)src)[j];
        float4 hi, lo;
        hi.x = rna(v.x); lo.x = rna(v.x - hi.x);
        hi.y = rna(v.y); lo.y = rna(v.y - hi.y);
        hi.z = rna(v.z); lo.z = rna(v.z - hi.z);
        hi.w = rna(v.w); lo.w = rna(v.w - hi.w);
        ((float4*)dhi)[j] = hi;
        ((float4*)dlo)[j] = lo;
    } else if (blk < 3264) {
        const int i = (blk - 2240) * 256 + t;        // float4 idx
        const float* src; float* dst; int j;
        if (i < 131072) { src = W_gcn; dst = g_wgr; j = i; }
        else            { src = W_out; dst = g_wor; j = i - 131072; }
        float4 v = ((const float4*)src)[j];
        v.x = rna(v.x); v.y = rna(v.y); v.z = rna(v.z); v.w = rna(v.w);
        ((float4*)dst)[j] = v;
    } else {
        // adj pack, 4 int4 loads per thread (MLP=4; 64B contiguous/thread)
        const int i = (blk - 3264) * 256 + t;        // 16-int group idx (262144)
        const int4* src = (const int4*)adj + (size_t)i * 4;
        int4 w0 = src[0];
        int4 w1 = src[1];
        int4 w2 = src[2];
        int4 w3 = src[3];
        uint32_t bits =
            ((uint32_t)(w0.x != 0))       | ((uint32_t)(w0.y != 0) << 1)  |
            ((uint32_t)(w0.z != 0) << 2)  | ((uint32_t)(w0.w != 0) << 3)  |
            ((uint32_t)(w1.x != 0) << 4)  | ((uint32_t)(w1.y != 0) << 5)  |
            ((uint32_t)(w1.z != 0) << 6)  | ((uint32_t)(w1.w != 0) << 7)  |
            ((uint32_t)(w2.x != 0) << 8)  | ((uint32_t)(w2.y != 0) << 9)  |
            ((uint32_t)(w2.z != 0) << 10) | ((uint32_t)(w2.w != 0) << 11) |
            ((uint32_t)(w3.x != 0) << 12) | ((uint32_t)(w3.y != 0) << 13) |
            ((uint32_t)(w3.z != 0) << 14) | ((uint32_t)(w3.w != 0) << 15);
        uint32_t val = bits << ((i & 1) * 16);
        val |= __shfl_xor_sync(0xffffffffu, val, 1);
        if ((t & 1) == 0) g_adjbits[i >> 1] = val;
    }
}

// ===========================================================================
// Scores via 3xTF32 (hi/lo): grid (8 ntiles, 8 mtiles, 16 bh), 256 thr.
// 2-phase K-split pipeline: load K-half0 of all 4 tiles (group A), K-half1
// (group B); compute kk 0..3 overlapped with group B's arrival.
// Same kk order as before -> bit-identical accumulation.
// ===========================================================================
constexpr int SC_STR = 68;
constexpr int SC_TILE = 128 * SC_STR;
constexpr int SC_SMEM = 4 * SC_TILE * 4;

#define EPILOGUE_LOOP8(BODY)                                                  \
    do {                                                                      \
        const int lane = threadIdx.x & 31, wid = threadIdx.x >> 5;            \
        const int wm = (wid >> 1) * 32, wn = (wid & 1) * 64;                  \
        const int qr = lane >> 2, qk = lane & 3;                              \
        _Pragma("unroll")                                                     \
        for (int mi = 0; mi < 2; mi++)                                        \
            _Pragma("unroll")                                                 \
            for (int half = 0; half < 2; half++) {                            \
                const int row = wm + mi * 16 + qr + half * 8;                 \
                _Pragma("unroll")                                             \
                for (int ni = 0; ni < 8; ni++) {                              \
                    const int col = wn + ni * 8 + 2 * qk;                     \
                    float v0 = c[mi][ni][half * 2 + 0];                       \
                    float v1 = c[mi][ni][half * 2 + 1];                       \
                    BODY                                                      \
                }                                                             \
            }                                                                 \
    } while (0)

__global__ __launch_bounds__(256) void scores3_mma() {
    extern __shared__ uint32_t sm[];
    const int bh = blockIdx.z, b = bh >> 2, h = bh & 3;
    const int m0 = blockIdx.y * 128, n0 = blockIdx.x * 128;
    const int tid = threadIdx.x;
    const uint32_t sb = smem_u32(sm);

    const size_t qoff = ((size_t)(b * N_ + m0)) * D_ + h * 64;
    const size_t koff = ((size_t)(b * N_ + n0)) * D_ + h * 64;
    const float* srcs[4] = {g_qhi + qoff, g_qlo + qoff, g_khi + koff, g_klo + koff};

    // group A: K columns 0..31 of all 4 tiles (c4 0..7)
#pragma unroll
    for (int t = 0; t < 4; t++) {
        const uint32_t dst = sb + (uint32_t)(t * SC_TILE) * 4u;
        const float* s = srcs[t];
#pragma unroll
        for (int e = 0; e < 4; e++) {
            int idx = tid + 256 * e;          // 1024 = 128 rows x 8 c4
            int row = idx >> 3;
            int c4 = idx & 7;
            CP_A16(dst + (uint32_t)(row * SC_STR + c4 * 4) * 4u,
                   s + (size_t)row * D_ + c4 * 4);
        }
    }
    CP_COMMIT();
    // group B: K columns 32..63 (c4 8..15)
#pragma unroll
    for (int t = 0; t < 4; t++) {
        const uint32_t dst = sb + (uint32_t)(t * SC_TILE) * 4u;
        const float* s = srcs[t];
#pragma unroll
        for (int e = 0; e < 4; e++) {
            int idx = tid + 256 * e;
            int row = idx >> 3;
            int c4 = (idx & 7) + 8;
            CP_A16(dst + (uint32_t)(row * SC_STR + c4 * 4) * 4u,
                   s + (size_t)row * D_ + c4 * 4);
        }
    }
    CP_COMMIT();

    const uint32_t* sQh = sm;
    const uint32_t* sQl = sm + SC_TILE;
    const uint32_t* sKh = sm + 2 * SC_TILE;
    const uint32_t* sKl = sm + 3 * SC_TILE;

    const int lane = tid & 31, wid = tid >> 5;
    const int wm = (wid >> 1) * 32, wn = (wid & 1) * 64;
    const int qr = lane >> 2, qk = lane & 3;

    float c[2][8][4] = {};

    CP_WAIT(1);                   // group A resident; B still streaming
    __syncthreads();

#pragma unroll
    for (int phase = 0; phase < 2; phase++) {
        if (phase == 1) {
            CP_WAIT(0);           // group B resident
            __syncthreads();
        }
#pragma unroll
        for (int kh = 0; kh < 4; kh++) {
            const int kk = phase * 4 + kh;
            const int k0 = kk * 8;
            uint32_t ah[2][4], al[2][4];
#pragma unroll
            for (int mi = 0; mi < 2; mi++) {
                const int rb = wm + mi * 16 + qr;
                ah[mi][0] = sQh[(rb)     * SC_STR + k0 + qk];
                ah[mi][1] = sQh[(rb + 8) * SC_STR + k0 + qk];
                ah[mi][2] = sQh[(rb)     * SC_STR + k0 + qk + 4];
                ah[mi][3] = sQh[(rb + 8) * SC_STR + k0 + qk + 4];
                al[mi][0] = sQl[(rb)     * SC_STR + k0 + qk];
                al[mi][1] = sQl[(rb + 8) * SC_STR + k0 + qk];
                al[mi][2] = sQl[(rb)     * SC_STR + k0 + qk + 4];
                al[mi][3] = sQl[(rb + 8) * SC_STR + k0 + qk + 4];
            }
#pragma unroll
            for (int ni = 0; ni < 8; ni++) {
                const int nr = wn + ni * 8 + qr;
                uint32_t bh2[2], bl2[2];
                bh2[0] = sKh[nr * SC_STR + k0 + qk];
                bh2[1] = sKh[nr * SC_STR + k0 + qk + 4];
                bl2[0] = sKl[nr * SC_STR + k0 + qk];
                bl2[1] = sKl[nr * SC_STR + k0 + qk + 4];
#pragma unroll
                for (int mi = 0; mi < 2; mi++) {
                    mma16n8k8(c[mi][ni], ah[mi], bh2);
                    mma16n8k8(c[mi][ni], ah[mi], bl2);
                    mma16n8k8(c[mi][ni], al[mi], bh2);
                }
            }
        }
    }

    float* C = g_attn + (size_t)bh * N_ * N_ + (size_t)m0 * N_ + n0;
    EPILOGUE_LOOP8({
        *(float2*)(C + (size_t)row * N_ + col) = make_float2(v0, v1);
    });
}

// ---------------------------------------------------------------------------
// z-score attention — vectorized + merged reductions (R11/R15-measured)
// ---------------------------------------------------------------------------
__device__ __forceinline__ void blockReduce3(float& a, float& b, float& m,
                                             float* sbuf) {
    const int tid = threadIdx.x;
#pragma unroll
    for (int o = 16; o > 0; o >>= 1) {
        a += __shfl_xor_sync(0xffffffffu, a, o);
        b += __shfl_xor_sync(0xffffffffu, b, o);
        m = fmaxf(m, __shfl_xor_sync(0xffffffffu, m, o));
    }
    if ((tid & 31) == 0) {
        int w = tid >> 5;
        sbuf[w] = a; sbuf[8 + w] = b; sbuf[16 + w] = m;
    }
    __syncthreads();
    if (tid < 8) {
        float aa = sbuf[tid], bb = sbuf[8 + tid], mm = sbuf[16 + tid];
#pragma unroll
        for (int o = 4; o > 0; o >>= 1) {
            aa += __shfl_xor_sync(0xffu, aa, o);
            bb += __shfl_xor_sync(0xffu, bb, o);
            mm = fmaxf(mm, __shfl_xor_sync(0xffu, mm, o));
        }
        if (tid == 0) { sbuf[0] = aa; sbuf[8] = bb; sbuf[16] = mm; }
    }
    __syncthreads();
    a = sbuf[0]; b = sbuf[8]; m = sbuf[16];
    __syncthreads();
}

__device__ __forceinline__ void blockReduce2(float& a, float& b, float* sbuf) {
    const int tid = threadIdx.x;
#pragma unroll
    for (int o = 16; o > 0; o >>= 1) {
        a += __shfl_xor_sync(0xffffffffu, a, o);
        b += __shfl_xor_sync(0xffffffffu, b, o);
    }
    if ((tid & 31) == 0) {
        int w = tid >> 5;
        sbuf[w] = a; sbuf[8 + w] = b;
    }
    __syncthreads();
    if (tid < 8) {
        float aa = sbuf[tid], bb = sbuf[8 + tid];
#pragma unroll
        for (int o = 4; o > 0; o >>= 1) {
            aa += __shfl_xor_sync(0xffu, aa, o);
            bb += __shfl_xor_sync(0xffu, bb, o);
        }
        if (tid == 0) { sbuf[0] = aa; sbuf[8] = bb; }
    }
    __syncthreads();
    a = sbuf[0]; b = sbuf[8];
    __syncthreads();
}

__device__ __forceinline__ float blockReduce1(float v, float* sbuf) {
    const int tid = threadIdx.x;
#pragma unroll
    for (int o = 16; o > 0; o >>= 1) v += __shfl_xor_sync(0xffffffffu, v, o);
    if ((tid & 31) == 0) sbuf[tid >> 5] = v;
    __syncthreads();
    if (tid < 8) {
        v = sbuf[tid];
#pragma unroll
        for (int o = 4; o > 0; o >>= 1) v += __shfl_xor_sync(0xffu, v, o);
        if (tid == 0) sbuf[0] = v;
    }
    __syncthreads();
    float r = sbuf[0];
    __syncthreads();
    return r;
}

__global__ __launch_bounds__(256) void zscore_kernel(const int* __restrict__ mask) {
    const int row = blockIdx.x;
    const int i  = row & (N_ - 1);
    const int bh = row >> 10;
    const int b  = bh >> 2;
    float* sc = g_attn + (size_t)row * N_;
    const uint32_t* abits = g_adjbits + ((size_t)b * N_ + i) * (N_ / 32);
    const int* mrow = mask + (size_t)b * N_;
    const int tid = threadIdx.x;
    __shared__ float sbuf[24];

    const float4 v4 = ((const float4*)sc)[tid];
    const int4  m4 = ((const int4*)mrow)[tid];
    const uint32_t aw = abits[tid >> 3];
    const int bitbase = (tid & 7) * 4;

    float v[4] = {v4.x, v4.y, v4.z, v4.w};
    const int mvi[4] = {m4.x == 0, m4.y == 0, m4.z == 0, m4.w == 0};
    float av[4];
#pragma unroll
    for (int e = 0; e < 4; e++) av[e] = (float)((aw >> (bitbase + e)) & 1u);

    float cnt = 0.f, s = 0.f, maxv = -1e30f;
#pragma unroll
    for (int e = 0; e < 4; e++) {
        if (mvi[e]) { cnt += 1.f; s += v[e]; maxv = fmaxf(maxv, v[e]); }
    }
    blockReduce3(cnt, s, maxv, sbuf);
    const float mean = s / (cnt + 1e-4f);

    float ss = 0.f;
#pragma unroll
    for (int e = 0; e < 4; e++) {
        float d = v[e] - mean;
        if (mvi[e]) ss += d * d;
    }
    ss = blockReduce1(ss, sbuf);
    const float stdv = sqrtf(ss / (cnt + 1e-4f) + 1e-10f);
    const float invstd = 1.f / (stdv + 1e-4f);

    float mx = (maxv - mean) * invstd;
    if (!(mx >= 0.f)) mx = -1e9f;

    float s2[4];
    int keep[4];
#pragma unroll
    for (int e = 0; e < 4; e++) {
        float z = (v[e] - mean) * invstd;
        int ok = (mvi[e] && z >= 0.f);
        s2[e] = ok ? z : -1e9f;
        keep[e] = (ok && av[e] != 0.f);
    }

    float ev[4], se = 0.f, sk = 0.f;
#pragma unroll
    for (int e = 0; e < 4; e++) {
        float ee = mvi[e] ? (__expf(s2[e] - mx) * av[e]) : 0.f;
        ee += 1e-10f;
        ev[e] = ee;
        se += ee;
        if (keep[e]) sk += ee;
    }
    blockReduce2(se, sk, sbuf);
    const float invse = 1.f / se;

    float4 w4;
    w4.x = keep[0] ? rna(ev[0] * invse) : 0.f;
    w4.y = keep[1] ? rna(ev[1] * invse) : 0.f;
    w4.z = keep[2] ? rna(ev[2] * invse) : 0.f;
    w4.w = keep[3] ? rna(ev[3] * invse) : 0.f;
    ((float4*)sc)[tid] = w4;

    if (tid == 0) g_denom[row] = sk * invse + 1.f;
}

// ===========================================================================
extern "C" void kernel_launch(void* const* d_in, const int* in_sizes, int n_in,
                              void* d_out, int out_size) {
    const float* gcn   = (const float*)d_in[0];
    const float* rel   = (const float*)d_in[1];
    const int*   adj   = (const int*)d_in[2];
    const int*   mask  = (const int*)d_in[3];
    const float* W_Q   = (const float*)d_in[4];
    const float* b_Q   = (const float*)d_in[5];
    const float* W_K   = (const float*)d_in[6];
    const float* b_K   = (const float*)d_in[7];
    const float* W_gcn = (const float*)d_in[8];
    const float* b_gcn = (const float*)d_in[9];
    const float* W_out = (const float*)d_in[10];
    const float* b_out = (const float*)d_in[11];
    float* out = (float*)d_out;

    cudaFuncSetAttribute(proj_mma,    cudaFuncAttributeMaxDynamicSharedMemorySize, MMA_SMEM);
    cudaFuncSetAttribute(axpx_mma,    cudaFuncAttributeMaxDynamicSharedMemorySize, MMA_SMEM);
    cudaFuncSetAttribute(tw_mma,      cudaFuncAttributeMaxDynamicSharedMemorySize, MMA_SMEM);
    cudaFuncSetAttribute(final_mma,   cudaFuncAttributeMaxDynamicSharedMemorySize, MMA_SMEM);
    cudaFuncSetAttribute(scores3_mma, cudaFuncAttributeMaxDynamicSharedMemorySize, SC_SMEM);

    // prep (hi/lo splits, roundings, adj pack) — one launch
    prep_kernel<<<4288, 256>>>(gcn, rel, W_Q, W_K, W_gcn, W_out, adj);

    // projections on tensor cores (fp32-accurate)
    proj_mma<<<dim3(32, 2), 512, MMA_SMEM>>>(b_Q, b_K);

    // scores + z-score attention
    scores3_mma<<<dim3(8, 8, 16), 256, SC_SMEM>>>();
    zscore_kernel<<<16 * N_, 256>>>(mask);

    // GCN layers
    for (int l = 0; l < L_; l++) {
        axpx_mma<<<dim3(8, 16), 512, MMA_SMEM>>>(gcn, l);
        tw_mma<<<dim3(8, 16), 512, MMA_SMEM>>>(b_gcn, l);
    }

    // output projection: split-K + deterministic reduce
    final_mma<<<dim3(4, 32), 512, MMA_SMEM>>>();
    reduce_final<<<1024, 256>>>(gcn, b_out, out);
}